// round 10
// baseline (speedup 1.0000x reference)
#include <cuda_runtime.h>
#include <cstdint>

#define NN 50000
#define KD 512
#define EM 128
#define OD 64
#define EE 1600000

// ---------------- scratch (device globals) ----------------
__device__ float g_h[(size_t)NN * EM];
__device__ float g_g[(size_t)NN * OD];
__device__ float g_as[NN];
__device__ float g_ad[NN];
__device__ int   g_cnt[NN];
__device__ int   g_off[NN];
__device__ int   g_pos[NN];
__device__ int   g_esrc[EE];

__device__ __forceinline__ float to_tf32(float x) {
    float r;
    asm("cvt.rna.tf32.f32 %0, %1;" : "=f"(r) : "f"(x));
    return r;
}

// ---------------- CSR build ----------------
__global__ void k_hist(const int* __restrict__ ei, int E) {
    int i = blockIdx.x * blockDim.x + threadIdx.x;
    if (i < E) atomicAdd(g_cnt + ei[E + i], 1);
}

// single-block scan over 50K counts (hidden under GEMMs on stream 2)
__global__ __launch_bounds__(1024) void k_scan() {
    __shared__ int tsum[1024];
    const int CH = 49;                 // 1024*49 >= NN
    int t = threadIdx.x;
    int beg = t * CH;
    int end = min(beg + CH, NN);
    int s = 0;
    for (int i = beg; i < end; i++) s += g_cnt[i];
    tsum[t] = s;
    __syncthreads();
    for (int off = 1; off < 1024; off <<= 1) {
        int v = tsum[t];
        int u = (t >= off) ? tsum[t - off] : 0;
        __syncthreads();
        tsum[t] = v + u;
        __syncthreads();
    }
    int run = (t == 0) ? 0 : tsum[t - 1];
    for (int i = beg; i < end; i++) {
        g_off[i] = run;
        g_pos[i] = run;
        run += g_cnt[i];
    }
}

__global__ void k_scatter(const int* __restrict__ ei, int E) {
    int i = blockIdx.x * blockDim.x + threadIdx.x;
    if (i >= E) return;
    int s = ei[i];
    int d = ei[E + i];
    int p = atomicAdd(g_pos + d, 1);
    g_esrc[p] = s;
}

// ---------------- GEMM1: tf32 mma + 2-stage cp.async pipeline ----------------
// H = lrelu(X[NN,512] @ Wd[128,512]^T + bd). Block 128x128, BK=32, 16 K-chunks.
#define G1_BM 128
#define G1_BK 32
#define G1_ROW 36                   // 32 + 4 pad (floats per smem row)
#define G1_TILE (G1_BM * G1_ROW)    // floats per A/B tile
#define G1_SMEM (4 * G1_TILE * 4)   // bytes: 2 stages x (A + B)

__global__ __launch_bounds__(256) void k_gemm1(const float* __restrict__ X,
                                               const float* __restrict__ Wd,
                                               const float* __restrict__ bd) {
    extern __shared__ float smem[];
    float* As = smem;                 // [2][128][36]
    float* Bs = smem + 2 * G1_TILE;   // [2][128][36]
    const int tid  = threadIdx.x;
    const int warp = tid >> 5;
    const int lane = tid & 31;
    const int g    = lane >> 2;
    const int tig  = lane & 3;
    const int wm   = warp >> 2;
    const int wn   = warp & 3;
    const int row0 = blockIdx.x * G1_BM;

    const uint32_t a_base = (uint32_t)__cvta_generic_to_shared(As);
    const uint32_t b_base = (uint32_t)__cvta_generic_to_shared(Bs);

    float acc[4][4][4];
#pragma unroll
    for (int i = 0; i < 4; i++)
#pragma unroll
        for (int j = 0; j < 4; j++)
#pragma unroll
            for (int r = 0; r < 4; r++) acc[i][j][r] = 0.f;

    auto load_stage = [&](int st, int k0) {
#pragma unroll
        for (int i = 0; i < 4; i++) {
            int f  = tid + i * 256;          // 0..1023
            int r  = f >> 3;
            int kq = f & 7;
            int rg = row0 + r;
            if (rg > NN - 1) rg = NN - 1;    // clamp (stores masked in epilogue)
            const float* src = X + (size_t)rg * KD + k0 + kq * 4;
            uint32_t dst = a_base + (uint32_t)((st * G1_TILE + r * G1_ROW + kq * 4) * 4);
            asm volatile("cp.async.cg.shared.global [%0], [%1], 16;"
                         :: "r"(dst), "l"(src));
        }
#pragma unroll
        for (int i = 0; i < 4; i++) {
            int f  = tid + i * 256;
            int c  = f >> 3;
            int kq = f & 7;
            const float* src = Wd + (size_t)c * KD + k0 + kq * 4;
            uint32_t dst = b_base + (uint32_t)((st * G1_TILE + c * G1_ROW + kq * 4) * 4);
            asm volatile("cp.async.cg.shared.global [%0], [%1], 16;"
                         :: "r"(dst), "l"(src));
        }
        asm volatile("cp.async.commit_group;");
    };

    const int NCH = KD / G1_BK;   // 16
    load_stage(0, 0);
    for (int kt = 0; kt < NCH; kt++) {
        int st = kt & 1;
        if (kt + 1 < NCH) {
            load_stage(st ^ 1, (kt + 1) * G1_BK);
            asm volatile("cp.async.wait_group 1;");
        } else {
            asm volatile("cp.async.wait_group 0;");
        }
        __syncthreads();

        const float* A0 = As + st * G1_TILE;
        const float* B0 = Bs + st * G1_TILE;
#pragma unroll
        for (int ks = 0; ks < 4; ks++) {
            const int kb = ks * 8;
            uint32_t af[4][4];
#pragma unroll
            for (int mt = 0; mt < 4; mt++) {
                int ra = wm * 64 + mt * 16 + g;
                af[mt][0] = __float_as_uint(to_tf32(A0[ra * G1_ROW + kb + tig]));
                af[mt][1] = __float_as_uint(to_tf32(A0[(ra + 8) * G1_ROW + kb + tig]));
                af[mt][2] = __float_as_uint(to_tf32(A0[ra * G1_ROW + kb + tig + 4]));
                af[mt][3] = __float_as_uint(to_tf32(A0[(ra + 8) * G1_ROW + kb + tig + 4]));
            }
            uint32_t bf[4][2];
#pragma unroll
            for (int nt = 0; nt < 4; nt++) {
                int nb = wn * 32 + nt * 8 + g;
                bf[nt][0] = __float_as_uint(to_tf32(B0[nb * G1_ROW + kb + tig]));
                bf[nt][1] = __float_as_uint(to_tf32(B0[nb * G1_ROW + kb + tig + 4]));
            }
#pragma unroll
            for (int mt = 0; mt < 4; mt++)
#pragma unroll
                for (int nt = 0; nt < 4; nt++) {
                    asm volatile(
                        "mma.sync.aligned.m16n8k8.row.col.f32.tf32.tf32.f32 "
                        "{%0,%1,%2,%3}, {%4,%5,%6,%7}, {%8,%9}, {%0,%1,%2,%3};"
                        : "+f"(acc[mt][nt][0]), "+f"(acc[mt][nt][1]),
                          "+f"(acc[mt][nt][2]), "+f"(acc[mt][nt][3])
                        : "r"(af[mt][0]), "r"(af[mt][1]), "r"(af[mt][2]), "r"(af[mt][3]),
                          "r"(bf[nt][0]), "r"(bf[nt][1]));
                }
        }
        __syncthreads();   // stage consumed; next prefetch may overwrite it
    }

#pragma unroll
    for (int mt = 0; mt < 4; mt++) {
#pragma unroll
        for (int half = 0; half < 2; half++) {
            int r = row0 + wm * 64 + mt * 16 + g + half * 8;
            if (r >= NN) continue;
#pragma unroll
            for (int nt = 0; nt < 4; nt++) {
                int c = wn * 32 + nt * 8 + tig * 2;
                float v0 = acc[mt][nt][half * 2]     + __ldg(bd + c);
                float v1 = acc[mt][nt][half * 2 + 1] + __ldg(bd + c + 1);
                v0 = v0 > 0.f ? v0 : 0.01f * v0;
                v1 = v1 > 0.f ? v1 : 0.01f * v1;
                *reinterpret_cast<float2*>(g_h + (size_t)r * EM + c) = make_float2(v0, v1);
            }
        }
    }
}

// ---------------- GEMM2 (tensor cores) + attention logits ----------------
#define G2_BM 128
#define G2_LDS 36
__global__ __launch_bounds__(256) void k_gemm2(const float* __restrict__ Wg,
                                               const float* __restrict__ att_s,
                                               const float* __restrict__ att_d) {
    __shared__ float As[G2_BM][G2_LDS];
    __shared__ float Bs[OD][G2_LDS];
    __shared__ float ps_sh[G2_BM][2], pd_sh[G2_BM][2];
    __shared__ float ats[OD], atd[OD];
    const int tid  = threadIdx.x;
    const int warp = tid >> 5;
    const int lane = tid & 31;
    const int g    = lane >> 2;
    const int tig  = lane & 3;
    const int wm   = warp >> 1;
    const int wn   = warp & 1;
    const int row0 = blockIdx.x * G2_BM;

    if (tid < OD) { ats[tid] = att_s[tid]; atd[tid] = att_d[tid]; }

    float acc[2][4][4];
#pragma unroll
    for (int i = 0; i < 2; i++)
#pragma unroll
        for (int j = 0; j < 4; j++)
#pragma unroll
            for (int r = 0; r < 4; r++) acc[i][j][r] = 0.f;

    for (int k0 = 0; k0 < EM; k0 += 32) {
#pragma unroll
        for (int i = 0; i < 4; i++) {
            int f  = tid + i * 256;
            int r  = f >> 3;
            int kq = f & 7;
            float4 v = make_float4(0.f, 0.f, 0.f, 0.f);
            int rg = row0 + r;
            if (rg < NN)
                v = *reinterpret_cast<const float4*>(g_h + (size_t)rg * EM + k0 + kq * 4);
            v.x = to_tf32(v.x); v.y = to_tf32(v.y);
            v.z = to_tf32(v.z); v.w = to_tf32(v.w);
            *reinterpret_cast<float4*>(&As[r][kq * 4]) = v;
        }
#pragma unroll
        for (int i = 0; i < 2; i++) {
            int f  = tid + i * 256;
            int c  = f >> 3;
            int kq = f & 7;
            float4 v = *reinterpret_cast<const float4*>(Wg + (size_t)c * EM + k0 + kq * 4);
            v.x = to_tf32(v.x); v.y = to_tf32(v.y);
            v.z = to_tf32(v.z); v.w = to_tf32(v.w);
            *reinterpret_cast<float4*>(&Bs[c][kq * 4]) = v;
        }
        __syncthreads();
#pragma unroll
        for (int ks = 0; ks < 4; ks++) {
            const int kb = ks * 8;
            uint32_t af[2][4];
#pragma unroll
            for (int mt = 0; mt < 2; mt++) {
                int ra = wm * 32 + mt * 16 + g;
                af[mt][0] = __float_as_uint(As[ra][kb + tig]);
                af[mt][1] = __float_as_uint(As[ra + 8][kb + tig]);
                af[mt][2] = __float_as_uint(As[ra][kb + tig + 4]);
                af[mt][3] = __float_as_uint(As[ra + 8][kb + tig + 4]);
            }
            uint32_t bf[4][2];
#pragma unroll
            for (int nt = 0; nt < 4; nt++) {
                int nb = wn * 32 + nt * 8 + g;
                bf[nt][0] = __float_as_uint(Bs[nb][kb + tig]);
                bf[nt][1] = __float_as_uint(Bs[nb][kb + tig + 4]);
            }
#pragma unroll
            for (int mt = 0; mt < 2; mt++)
#pragma unroll
                for (int nt = 0; nt < 4; nt++) {
                    asm volatile(
                        "mma.sync.aligned.m16n8k8.row.col.f32.tf32.tf32.f32 "
                        "{%0,%1,%2,%3}, {%4,%5,%6,%7}, {%8,%9}, {%0,%1,%2,%3};"
                        : "+f"(acc[mt][nt][0]), "+f"(acc[mt][nt][1]),
                          "+f"(acc[mt][nt][2]), "+f"(acc[mt][nt][3])
                        : "r"(af[mt][0]), "r"(af[mt][1]), "r"(af[mt][2]), "r"(af[mt][3]),
                          "r"(bf[nt][0]), "r"(bf[nt][1]));
                }
        }
        __syncthreads();
    }

#pragma unroll
    for (int mt = 0; mt < 2; mt++) {
#pragma unroll
        for (int half = 0; half < 2; half++) {
            int rloc = wm * 32 + mt * 16 + g + half * 8;
            int r = row0 + rloc;
            float ps = 0.f, pd = 0.f;
#pragma unroll
            for (int nt = 0; nt < 4; nt++) {
                int c = wn * 32 + nt * 8 + tig * 2;
                float v0 = acc[mt][nt][half * 2];
                float v1 = acc[mt][nt][half * 2 + 1];
                if (r < NN)
                    *reinterpret_cast<float2*>(g_g + (size_t)r * OD + c) = make_float2(v0, v1);
                ps = fmaf(v0, ats[c], fmaf(v1, ats[c + 1], ps));
                pd = fmaf(v0, atd[c], fmaf(v1, atd[c + 1], pd));
            }
            ps += __shfl_xor_sync(0xffffffffu, ps, 1);
            ps += __shfl_xor_sync(0xffffffffu, ps, 2);
            pd += __shfl_xor_sync(0xffffffffu, pd, 1);
            pd += __shfl_xor_sync(0xffffffffu, pd, 2);
            if (tig == 0) { ps_sh[rloc][wn] = ps; pd_sh[rloc][wn] = pd; }
        }
    }
    __syncthreads();
    if (tid < G2_BM) {
        int r = row0 + tid;
        if (r < NN) {
            g_as[r] = ps_sh[tid][0] + ps_sh[tid][1];
            g_ad[r] = pd_sh[tid][0] + pd_sh[tid][1];
        }
    }
}

// ---------------- fused softmax + gather accumulate (R8 version: known-good) ----------------
// 2 warps per dst (32 cols each). 32-edge batches, staged 32-deep SCALAR gather
// (fits registers; pad lanes gather the dst row with wt=0 -> L1 hits, no tail).
__global__ __launch_bounds__(256) void k_accum(float* __restrict__ out,
                                               const float* __restrict__ bg) {
    const unsigned FULL = 0xffffffffu;
    int W    = (blockIdx.x * blockDim.x + threadIdx.x) >> 5;
    int lane = threadIdx.x & 31;
    int dst  = W >> 1;
    int half = W & 1;
    if (dst >= NN) return;
    int col = half * 32 + lane;
    int beg = g_off[dst];
    int cnt = g_cnt[dst];
    float a_d = g_ad[dst];

    // self loop
    float e0 = g_as[dst] + a_d;
    e0 = e0 > 0.f ? e0 : 0.2f * e0;
    float wt_self = __expf(e0);
    float acc = wt_self * g_g[(size_t)dst * OD + col];
    float den_l = (lane == 0) ? wt_self : 0.f;

    int end = beg + cnt;
    for (int j = beg; j < end; j += 32) {
        int m = end - j;
        if (m > 32) m = 32;
        int   s_l  = dst;
        float wt_l = 0.f;
        if (lane < m) {
            s_l = g_esrc[j + lane];
            float e = g_as[s_l] + a_d;
            e = e > 0.f ? e : 0.2f * e;
            wt_l = __expf(e);
        }
        den_l += wt_l;
        float gvs[32];
#pragma unroll
        for (int u = 0; u < 32; u++) {
            int s = __shfl_sync(FULL, s_l, u);
            gvs[u] = g_g[(size_t)s * OD + col];
        }
#pragma unroll
        for (int u = 0; u < 32; u++) {
            float wt = __shfl_sync(FULL, wt_l, u);
            acc = fmaf(wt, gvs[u], acc);
        }
    }
#pragma unroll
    for (int o = 16; o > 0; o >>= 1)
        den_l += __shfl_xor_sync(FULL, den_l, o);
    out[(size_t)dst * OD + col] = acc / den_l + __ldg(bg + col);
}

// ---------------- launch ----------------
extern "C" void kernel_launch(void* const* d_in, const int* in_sizes, int n_in,
                              void* d_out, int out_size) {
    const float* x   = (const float*)d_in[0];
    const int*   ei  = (const int*)  d_in[1];
    const float* Wd  = (const float*)d_in[2];
    const float* bd  = (const float*)d_in[3];
    const float* Wg  = (const float*)d_in[4];
    const float* ats = (const float*)d_in[5];
    const float* atd = (const float*)d_in[6];
    const float* bg  = (const float*)d_in[7];
    float* out = (float*)d_out;

    const int E = in_sizes[1] / 2;

    static cudaStream_t s2 = nullptr;
    static cudaEvent_t ev_fork = nullptr, ev_join = nullptr;
    static void* cnt_ptr = nullptr;
    if (!s2) {
        cudaStreamCreate(&s2);
        cudaEventCreateWithFlags(&ev_fork, cudaEventDisableTiming);
        cudaEventCreateWithFlags(&ev_join, cudaEventDisableTiming);
        cudaGetSymbolAddress(&cnt_ptr, g_cnt);
        cudaFuncSetAttribute(k_gemm1, cudaFuncAttributeMaxDynamicSharedMemorySize, G1_SMEM);
    }

    // fork: CSR build on s2 (memset is not a kernel launch -> gemm1 is 4th kernel)
    cudaEventRecord(ev_fork, 0);
    cudaStreamWaitEvent(s2, ev_fork, 0);

    cudaMemsetAsync(cnt_ptr, 0, NN * sizeof(int), s2);
    k_hist<<<(E + 255) / 256, 256, 0, s2>>>(ei, E);          // launch 1
    k_scan<<<1, 1024, 0, s2>>>();                            // launch 2
    k_scatter<<<(E + 255) / 256, 256, 0, s2>>>(ei, E);       // launch 3
    cudaEventRecord(ev_join, s2);

    k_gemm1<<<(NN + G1_BM - 1) / G1_BM, 256, G1_SMEM>>>(x, Wd, bd);   // launch 4 (profiled)
    k_gemm2<<<(NN + G2_BM - 1) / G2_BM, 256>>>(Wg, ats, atd);

    cudaStreamWaitEvent(0, ev_join, 0);
    {
        long long warps = (long long)NN * 2;
        int blocks = (int)((warps * 32 + 255) / 256);
        k_accum<<<blocks, 256>>>(out, bg);
    }
}

// round 11
// speedup vs baseline: 1.4158x; 1.4158x over previous
#include <cuda_runtime.h>
#include <cstdint>

#define NN 50000
#define KD 512
#define EM 128
#define OD 64
#define EE 1600000
#define SCAN_B 196            // 196 * 256 = 50176 >= NN

// ---------------- scratch (device globals) ----------------
__device__ float g_h[(size_t)NN * EM];
__device__ float g_g[(size_t)NN * OD];
__device__ float g_as[NN];
__device__ float g_ad[NN];
__device__ int   g_cnt[NN];
__device__ int   g_off[NN];
__device__ int   g_pos[NN];
__device__ int   g_esrc[EE];
__device__ int   g_bsum[SCAN_B];
__device__ int   g_boff[SCAN_B];

__device__ __forceinline__ float to_tf32(float x) {
    float r;
    asm("cvt.rna.tf32.f32 %0, %1;" : "=f"(r) : "f"(x));
    return r;
}

// ---------------- CSR build (parallel, coalesced) ----------------
__global__ void k_hist(const int* __restrict__ ei, int E) {
    int i = blockIdx.x * blockDim.x + threadIdx.x;
    if (i < E) atomicAdd(g_cnt + ei[E + i], 1);
}

__global__ __launch_bounds__(256) void k_scan1() {
    __shared__ int sh[256];
    int t = threadIdx.x;
    int i = blockIdx.x * 256 + t;
    int v = (i < NN) ? g_cnt[i] : 0;
    sh[t] = v;
    __syncthreads();
#pragma unroll
    for (int o = 128; o > 0; o >>= 1) {
        if (t < o) sh[t] += sh[t + o];
        __syncthreads();
    }
    if (t == 0) g_bsum[blockIdx.x] = sh[0];
}

__global__ __launch_bounds__(256) void k_scan2() {
    __shared__ int sh[256];
    int t = threadIdx.x;
    int v = (t < SCAN_B) ? g_bsum[t] : 0;
    sh[t] = v;
    __syncthreads();
#pragma unroll
    for (int o = 1; o < 256; o <<= 1) {
        int u = (t >= o) ? sh[t - o] : 0;
        __syncthreads();
        sh[t] += u;
        __syncthreads();
    }
    if (t < SCAN_B) g_boff[t] = sh[t] - v;
}

__global__ __launch_bounds__(256) void k_scan3() {
    __shared__ int sh[256];
    int t = threadIdx.x;
    int i = blockIdx.x * 256 + t;
    int v = (i < NN) ? g_cnt[i] : 0;
    sh[t] = v;
    __syncthreads();
#pragma unroll
    for (int o = 1; o < 256; o <<= 1) {
        int u = (t >= o) ? sh[t - o] : 0;
        __syncthreads();
        sh[t] += u;
        __syncthreads();
    }
    if (i < NN) {
        int off = g_boff[blockIdx.x] + sh[t] - v;
        g_off[i] = off;
        g_pos[i] = off;
    }
}

__global__ void k_scatter(const int* __restrict__ ei, int E) {
    int i = blockIdx.x * blockDim.x + threadIdx.x;
    if (i >= E) return;
    int s = ei[i];
    int d = ei[E + i];
    int p = atomicAdd(g_pos + d, 1);
    g_esrc[p] = s;
}

// ---------------- GEMM1: tf32 mma + 2-stage cp.async pipeline ----------------
#define G1_BM 128
#define G1_BK 32
#define G1_ROW 36
#define G1_TILE (G1_BM * G1_ROW)
#define G1_SMEM (4 * G1_TILE * 4)

__global__ __launch_bounds__(256) void k_gemm1(const float* __restrict__ X,
                                               const float* __restrict__ Wd,
                                               const float* __restrict__ bd) {
    extern __shared__ float smem[];
    float* As = smem;                 // [2][128][36]
    float* Bs = smem + 2 * G1_TILE;   // [2][128][36]
    const int tid  = threadIdx.x;
    const int warp = tid >> 5;
    const int lane = tid & 31;
    const int g    = lane >> 2;
    const int tig  = lane & 3;
    const int wm   = warp >> 2;
    const int wn   = warp & 3;
    const int row0 = blockIdx.x * G1_BM;

    const uint32_t a_base = (uint32_t)__cvta_generic_to_shared(As);
    const uint32_t b_base = (uint32_t)__cvta_generic_to_shared(Bs);

    float acc[4][4][4];
#pragma unroll
    for (int i = 0; i < 4; i++)
#pragma unroll
        for (int j = 0; j < 4; j++)
#pragma unroll
            for (int r = 0; r < 4; r++) acc[i][j][r] = 0.f;

    auto load_stage = [&](int st, int k0) {
#pragma unroll
        for (int i = 0; i < 4; i++) {
            int f  = tid + i * 256;
            int r  = f >> 3;
            int kq = f & 7;
            int rg = row0 + r;
            if (rg > NN - 1) rg = NN - 1;    // clamp (stores masked in epilogue)
            const float* src = X + (size_t)rg * KD + k0 + kq * 4;
            uint32_t dst = a_base + (uint32_t)((st * G1_TILE + r * G1_ROW + kq * 4) * 4);
            asm volatile("cp.async.cg.shared.global [%0], [%1], 16;"
                         :: "r"(dst), "l"(src));
        }
#pragma unroll
        for (int i = 0; i < 4; i++) {
            int f  = tid + i * 256;
            int c  = f >> 3;
            int kq = f & 7;
            const float* src = Wd + (size_t)c * KD + k0 + kq * 4;
            uint32_t dst = b_base + (uint32_t)((st * G1_TILE + c * G1_ROW + kq * 4) * 4);
            asm volatile("cp.async.cg.shared.global [%0], [%1], 16;"
                         :: "r"(dst), "l"(src));
        }
        asm volatile("cp.async.commit_group;");
    };

    const int NCH = KD / G1_BK;   // 16
    load_stage(0, 0);
    for (int kt = 0; kt < NCH; kt++) {
        int st = kt & 1;
        if (kt + 1 < NCH) {
            load_stage(st ^ 1, (kt + 1) * G1_BK);
            asm volatile("cp.async.wait_group 1;");
        } else {
            asm volatile("cp.async.wait_group 0;");
        }
        __syncthreads();

        const float* A0 = As + st * G1_TILE;
        const float* B0 = Bs + st * G1_TILE;
#pragma unroll
        for (int ks = 0; ks < 4; ks++) {
            const int kb = ks * 8;
            uint32_t af[4][4];
#pragma unroll
            for (int mt = 0; mt < 4; mt++) {
                int ra = wm * 64 + mt * 16 + g;
                af[mt][0] = __float_as_uint(to_tf32(A0[ra * G1_ROW + kb + tig]));
                af[mt][1] = __float_as_uint(to_tf32(A0[(ra + 8) * G1_ROW + kb + tig]));
                af[mt][2] = __float_as_uint(to_tf32(A0[ra * G1_ROW + kb + tig + 4]));
                af[mt][3] = __float_as_uint(to_tf32(A0[(ra + 8) * G1_ROW + kb + tig + 4]));
            }
            uint32_t bf[4][2];
#pragma unroll
            for (int nt = 0; nt < 4; nt++) {
                int nb = wn * 32 + nt * 8 + g;
                bf[nt][0] = __float_as_uint(to_tf32(B0[nb * G1_ROW + kb + tig]));
                bf[nt][1] = __float_as_uint(to_tf32(B0[nb * G1_ROW + kb + tig + 4]));
            }
#pragma unroll
            for (int mt = 0; mt < 4; mt++)
#pragma unroll
                for (int nt = 0; nt < 4; nt++) {
                    asm volatile(
                        "mma.sync.aligned.m16n8k8.row.col.f32.tf32.tf32.f32 "
                        "{%0,%1,%2,%3}, {%4,%5,%6,%7}, {%8,%9}, {%0,%1,%2,%3};"
                        : "+f"(acc[mt][nt][0]), "+f"(acc[mt][nt][1]),
                          "+f"(acc[mt][nt][2]), "+f"(acc[mt][nt][3])
                        : "r"(af[mt][0]), "r"(af[mt][1]), "r"(af[mt][2]), "r"(af[mt][3]),
                          "r"(bf[nt][0]), "r"(bf[nt][1]));
                }
        }
        __syncthreads();
    }

#pragma unroll
    for (int mt = 0; mt < 4; mt++) {
#pragma unroll
        for (int half = 0; half < 2; half++) {
            int r = row0 + wm * 64 + mt * 16 + g + half * 8;
            if (r >= NN) continue;
#pragma unroll
            for (int nt = 0; nt < 4; nt++) {
                int c = wn * 32 + nt * 8 + tig * 2;
                float v0 = acc[mt][nt][half * 2]     + __ldg(bd + c);
                float v1 = acc[mt][nt][half * 2 + 1] + __ldg(bd + c + 1);
                v0 = v0 > 0.f ? v0 : 0.01f * v0;
                v1 = v1 > 0.f ? v1 : 0.01f * v1;
                *reinterpret_cast<float2*>(g_h + (size_t)r * EM + c) = make_float2(v0, v1);
            }
        }
    }
}

// ---------------- GEMM2 (tensor cores) + attention logits ----------------
#define G2_BM 128
#define G2_LDS 36
__global__ __launch_bounds__(256) void k_gemm2(const float* __restrict__ Wg,
                                               const float* __restrict__ att_s,
                                               const float* __restrict__ att_d) {
    __shared__ float As[G2_BM][G2_LDS];
    __shared__ float Bs[OD][G2_LDS];
    __shared__ float ps_sh[G2_BM][2], pd_sh[G2_BM][2];
    __shared__ float ats[OD], atd[OD];
    const int tid  = threadIdx.x;
    const int warp = tid >> 5;
    const int lane = tid & 31;
    const int g    = lane >> 2;
    const int tig  = lane & 3;
    const int wm   = warp >> 1;
    const int wn   = warp & 1;
    const int row0 = blockIdx.x * G2_BM;

    if (tid < OD) { ats[tid] = att_s[tid]; atd[tid] = att_d[tid]; }

    float acc[2][4][4];
#pragma unroll
    for (int i = 0; i < 2; i++)
#pragma unroll
        for (int j = 0; j < 4; j++)
#pragma unroll
            for (int r = 0; r < 4; r++) acc[i][j][r] = 0.f;

    for (int k0 = 0; k0 < EM; k0 += 32) {
#pragma unroll
        for (int i = 0; i < 4; i++) {
            int f  = tid + i * 256;
            int r  = f >> 3;
            int kq = f & 7;
            float4 v = make_float4(0.f, 0.f, 0.f, 0.f);
            int rg = row0 + r;
            if (rg < NN)
                v = *reinterpret_cast<const float4*>(g_h + (size_t)rg * EM + k0 + kq * 4);
            v.x = to_tf32(v.x); v.y = to_tf32(v.y);
            v.z = to_tf32(v.z); v.w = to_tf32(v.w);
            *reinterpret_cast<float4*>(&As[r][kq * 4]) = v;
        }
#pragma unroll
        for (int i = 0; i < 2; i++) {
            int f  = tid + i * 256;
            int c  = f >> 3;
            int kq = f & 7;
            float4 v = *reinterpret_cast<const float4*>(Wg + (size_t)c * EM + k0 + kq * 4);
            v.x = to_tf32(v.x); v.y = to_tf32(v.y);
            v.z = to_tf32(v.z); v.w = to_tf32(v.w);
            *reinterpret_cast<float4*>(&Bs[c][kq * 4]) = v;
        }
        __syncthreads();
#pragma unroll
        for (int ks = 0; ks < 4; ks++) {
            const int kb = ks * 8;
            uint32_t af[2][4];
#pragma unroll
            for (int mt = 0; mt < 2; mt++) {
                int ra = wm * 32 + mt * 16 + g;
                af[mt][0] = __float_as_uint(As[ra][kb + tig]);
                af[mt][1] = __float_as_uint(As[ra + 8][kb + tig]);
                af[mt][2] = __float_as_uint(As[ra][kb + tig + 4]);
                af[mt][3] = __float_as_uint(As[ra + 8][kb + tig + 4]);
            }
            uint32_t bf[4][2];
#pragma unroll
            for (int nt = 0; nt < 4; nt++) {
                int nb = wn * 32 + nt * 8 + g;
                bf[nt][0] = __float_as_uint(Bs[nb][kb + tig]);
                bf[nt][1] = __float_as_uint(Bs[nb][kb + tig + 4]);
            }
#pragma unroll
            for (int mt = 0; mt < 2; mt++)
#pragma unroll
                for (int nt = 0; nt < 4; nt++) {
                    asm volatile(
                        "mma.sync.aligned.m16n8k8.row.col.f32.tf32.tf32.f32 "
                        "{%0,%1,%2,%3}, {%4,%5,%6,%7}, {%8,%9}, {%0,%1,%2,%3};"
                        : "+f"(acc[mt][nt][0]), "+f"(acc[mt][nt][1]),
                          "+f"(acc[mt][nt][2]), "+f"(acc[mt][nt][3])
                        : "r"(af[mt][0]), "r"(af[mt][1]), "r"(af[mt][2]), "r"(af[mt][3]),
                          "r"(bf[nt][0]), "r"(bf[nt][1]));
                }
        }
        __syncthreads();
    }

#pragma unroll
    for (int mt = 0; mt < 2; mt++) {
#pragma unroll
        for (int half = 0; half < 2; half++) {
            int rloc = wm * 32 + mt * 16 + g + half * 8;
            int r = row0 + rloc;
            float ps = 0.f, pd = 0.f;
#pragma unroll
            for (int nt = 0; nt < 4; nt++) {
                int c = wn * 32 + nt * 8 + tig * 2;
                float v0 = acc[mt][nt][half * 2];
                float v1 = acc[mt][nt][half * 2 + 1];
                if (r < NN)
                    *reinterpret_cast<float2*>(g_g + (size_t)r * OD + c) = make_float2(v0, v1);
                ps = fmaf(v0, ats[c], fmaf(v1, ats[c + 1], ps));
                pd = fmaf(v0, atd[c], fmaf(v1, atd[c + 1], pd));
            }
            ps += __shfl_xor_sync(0xffffffffu, ps, 1);
            ps += __shfl_xor_sync(0xffffffffu, ps, 2);
            pd += __shfl_xor_sync(0xffffffffu, pd, 1);
            pd += __shfl_xor_sync(0xffffffffu, pd, 2);
            if (tig == 0) { ps_sh[rloc][wn] = ps; pd_sh[rloc][wn] = pd; }
        }
    }
    __syncthreads();
    if (tid < G2_BM) {
        int r = row0 + tid;
        if (r < NN) {
            g_as[r] = ps_sh[tid][0] + ps_sh[tid][1];
            g_ad[r] = pd_sh[tid][0] + pd_sh[tid][1];
        }
    }
}

// ---------------- fused softmax + gather accumulate (R8 exact: known-good) ----------------
__global__ __launch_bounds__(256) void k_accum(float* __restrict__ out,
                                               const float* __restrict__ bg) {
    const unsigned FULL = 0xffffffffu;
    int W    = (blockIdx.x * blockDim.x + threadIdx.x) >> 5;
    int lane = threadIdx.x & 31;
    int dst  = W >> 1;
    int half = W & 1;
    if (dst >= NN) return;
    int col = half * 32 + lane;
    int beg = g_off[dst];
    int cnt = g_cnt[dst];
    float a_d = g_ad[dst];

    float e0 = g_as[dst] + a_d;
    e0 = e0 > 0.f ? e0 : 0.2f * e0;
    float wt_self = __expf(e0);
    float acc = wt_self * g_g[(size_t)dst * OD + col];
    float den_l = (lane == 0) ? wt_self : 0.f;

    int end = beg + cnt;
    for (int j = beg; j < end; j += 32) {
        int m = end - j;
        if (m > 32) m = 32;
        int   s_l  = dst;
        float wt_l = 0.f;
        if (lane < m) {
            s_l = g_esrc[j + lane];
            float e = g_as[s_l] + a_d;
            e = e > 0.f ? e : 0.2f * e;
            wt_l = __expf(e);
        }
        den_l += wt_l;
        float gvs[32];
#pragma unroll
        for (int u = 0; u < 32; u++) {
            int s = __shfl_sync(FULL, s_l, u);
            gvs[u] = g_g[(size_t)s * OD + col];
        }
#pragma unroll
        for (int u = 0; u < 32; u++) {
            float wt = __shfl_sync(FULL, wt_l, u);
            acc = fmaf(wt, gvs[u], acc);
        }
    }
#pragma unroll
    for (int o = 16; o > 0; o >>= 1)
        den_l += __shfl_xor_sync(FULL, den_l, o);
    out[(size_t)dst * OD + col] = acc / den_l + __ldg(bg + col);
}

// ---------------- launch ----------------
extern "C" void kernel_launch(void* const* d_in, const int* in_sizes, int n_in,
                              void* d_out, int out_size) {
    const float* x   = (const float*)d_in[0];
    const int*   ei  = (const int*)  d_in[1];
    const float* Wd  = (const float*)d_in[2];
    const float* bd  = (const float*)d_in[3];
    const float* Wg  = (const float*)d_in[4];
    const float* ats = (const float*)d_in[5];
    const float* atd = (const float*)d_in[6];
    const float* bg  = (const float*)d_in[7];
    float* out = (float*)d_out;

    const int E = in_sizes[1] / 2;

    static cudaStream_t s2 = nullptr;
    static cudaEvent_t ev_fork = nullptr, ev_join = nullptr;
    static void* cnt_ptr = nullptr;
    if (!s2) {
        cudaStreamCreate(&s2);
        cudaEventCreateWithFlags(&ev_fork, cudaEventDisableTiming);
        cudaEventCreateWithFlags(&ev_join, cudaEventDisableTiming);
        cudaGetSymbolAddress(&cnt_ptr, g_cnt);
        cudaFuncSetAttribute(k_gemm1, cudaFuncAttributeMaxDynamicSharedMemorySize, G1_SMEM);
    }

    // fork: CSR build on s2 (memset is not a kernel launch)
    cudaEventRecord(ev_fork, 0);
    cudaStreamWaitEvent(s2, ev_fork, 0);

    cudaMemsetAsync(cnt_ptr, 0, NN * sizeof(int), s2);
    k_hist<<<(E + 255) / 256, 256, 0, s2>>>(ei, E);          // launch 1
    k_scan1<<<SCAN_B, 256, 0, s2>>>();                       // launch 2
    k_scan2<<<1, 256, 0, s2>>>();                            // launch 3

    k_gemm1<<<(NN + G1_BM - 1) / G1_BM, 256, G1_SMEM>>>(x, Wd, bd);  // launch 4 (profiled)

    k_scan3<<<SCAN_B, 256, 0, s2>>>();                       // launch 5
    k_scatter<<<(E + 255) / 256, 256, 0, s2>>>(ei, E);       // launch 6
    cudaEventRecord(ev_join, s2);

    k_gemm2<<<(NN + G2_BM - 1) / G2_BM, 256>>>(Wg, ats, atd);

    cudaStreamWaitEvent(0, ev_join, 0);
    {
        long long warps = (long long)NN * 2;
        int blocks = (int)((warps * 32 + 255) / 256);
        k_accum<<<blocks, 256>>>(out, bg);
    }
}

// round 12
// speedup vs baseline: 1.7972x; 1.2694x over previous
#include <cuda_runtime.h>
#include <cstdint>

#define NN 50000
#define KD 512
#define EM 128
#define OD 64
#define EE 1600000
#define SCAN_B 196            // 196 * 256 = 50176 >= NN

// ---------------- scratch (device globals) ----------------
__device__ float g_h[(size_t)NN * EM];
__device__ float g_g[(size_t)NN * OD];
__device__ float g_as[NN];
__device__ float g_ad[NN];
__device__ int   g_cnt[NN];
__device__ int   g_off[NN];
__device__ int   g_pos[NN];
__device__ int   g_esrc[EE];
__device__ int   g_bsum[SCAN_B];
__device__ int   g_boff[SCAN_B];

__device__ __forceinline__ float to_tf32(float x) {
    float r;
    asm("cvt.rna.tf32.f32 %0, %1;" : "=f"(r) : "f"(x));
    return r;
}

// ---------------- CSR build (parallel, coalesced) ----------------
__global__ void k_hist(const int* __restrict__ ei, int E) {
    int i = blockIdx.x * blockDim.x + threadIdx.x;
    if (i < E) atomicAdd(g_cnt + ei[E + i], 1);
}

__global__ __launch_bounds__(256) void k_scan1() {
    __shared__ int sh[256];
    int t = threadIdx.x;
    int i = blockIdx.x * 256 + t;
    int v = (i < NN) ? g_cnt[i] : 0;
    sh[t] = v;
    __syncthreads();
#pragma unroll
    for (int o = 128; o > 0; o >>= 1) {
        if (t < o) sh[t] += sh[t + o];
        __syncthreads();
    }
    if (t == 0) g_bsum[blockIdx.x] = sh[0];
}

__global__ __launch_bounds__(256) void k_scan2() {
    __shared__ int sh[256];
    int t = threadIdx.x;
    int v = (t < SCAN_B) ? g_bsum[t] : 0;
    sh[t] = v;
    __syncthreads();
#pragma unroll
    for (int o = 1; o < 256; o <<= 1) {
        int u = (t >= o) ? sh[t - o] : 0;
        __syncthreads();
        sh[t] += u;
        __syncthreads();
    }
    if (t < SCAN_B) g_boff[t] = sh[t] - v;
}

__global__ __launch_bounds__(256) void k_scan3() {
    __shared__ int sh[256];
    int t = threadIdx.x;
    int i = blockIdx.x * 256 + t;
    int v = (i < NN) ? g_cnt[i] : 0;
    sh[t] = v;
    __syncthreads();
#pragma unroll
    for (int o = 1; o < 256; o <<= 1) {
        int u = (t >= o) ? sh[t - o] : 0;
        __syncthreads();
        sh[t] += u;
        __syncthreads();
    }
    if (i < NN) {
        int off = g_boff[blockIdx.x] + sh[t] - v;
        g_off[i] = off;
        g_pos[i] = off;
    }
}

__global__ void k_scatter(const int* __restrict__ ei, int E) {
    int i = blockIdx.x * blockDim.x + threadIdx.x;
    if (i >= E) return;
    int s = ei[i];
    int d = ei[E + i];
    int p = atomicAdd(g_pos + d, 1);
    g_esrc[p] = s;
}

// ---------------- GEMM1: tf32 mma + 2-stage cp.async pipeline ----------------
// Fragment loads feed raw fp32 bits to mma.tf32 (HW ignores low mantissa bits:
// implicit RZ rounding) — removes 96 CVTs per k-chunk per warp.
#define G1_BM 128
#define G1_BK 32
#define G1_ROW 36
#define G1_TILE (G1_BM * G1_ROW)
#define G1_SMEM (4 * G1_TILE * 4)

__global__ __launch_bounds__(256) void k_gemm1(const float* __restrict__ X,
                                               const float* __restrict__ Wd,
                                               const float* __restrict__ bd) {
    extern __shared__ float smem[];
    float* As = smem;                 // [2][128][36]
    float* Bs = smem + 2 * G1_TILE;   // [2][128][36]
    const int tid  = threadIdx.x;
    const int warp = tid >> 5;
    const int lane = tid & 31;
    const int g    = lane >> 2;
    const int tig  = lane & 3;
    const int wm   = warp >> 2;
    const int wn   = warp & 3;
    const int row0 = blockIdx.x * G1_BM;

    const uint32_t a_base = (uint32_t)__cvta_generic_to_shared(As);
    const uint32_t b_base = (uint32_t)__cvta_generic_to_shared(Bs);

    float acc[4][4][4];
#pragma unroll
    for (int i = 0; i < 4; i++)
#pragma unroll
        for (int j = 0; j < 4; j++)
#pragma unroll
            for (int r = 0; r < 4; r++) acc[i][j][r] = 0.f;

    auto load_stage = [&](int st, int k0) {
#pragma unroll
        for (int i = 0; i < 4; i++) {
            int f  = tid + i * 256;
            int r  = f >> 3;
            int kq = f & 7;
            int rg = row0 + r;
            if (rg > NN - 1) rg = NN - 1;    // clamp (stores masked in epilogue)
            const float* src = X + (size_t)rg * KD + k0 + kq * 4;
            uint32_t dst = a_base + (uint32_t)((st * G1_TILE + r * G1_ROW + kq * 4) * 4);
            asm volatile("cp.async.cg.shared.global [%0], [%1], 16;"
                         :: "r"(dst), "l"(src));
        }
#pragma unroll
        for (int i = 0; i < 4; i++) {
            int f  = tid + i * 256;
            int c  = f >> 3;
            int kq = f & 7;
            const float* src = Wd + (size_t)c * KD + k0 + kq * 4;
            uint32_t dst = b_base + (uint32_t)((st * G1_TILE + c * G1_ROW + kq * 4) * 4);
            asm volatile("cp.async.cg.shared.global [%0], [%1], 16;"
                         :: "r"(dst), "l"(src));
        }
        asm volatile("cp.async.commit_group;");
    };

    const int NCH = KD / G1_BK;   // 16
    load_stage(0, 0);
    for (int kt = 0; kt < NCH; kt++) {
        int st = kt & 1;
        if (kt + 1 < NCH) {
            load_stage(st ^ 1, (kt + 1) * G1_BK);
            asm volatile("cp.async.wait_group 1;");
        } else {
            asm volatile("cp.async.wait_group 0;");
        }
        __syncthreads();

        const float* A0 = As + st * G1_TILE;
        const float* B0 = Bs + st * G1_TILE;
#pragma unroll
        for (int ks = 0; ks < 4; ks++) {
            const int kb = ks * 8;
            uint32_t af[4][4];
#pragma unroll
            for (int mt = 0; mt < 4; mt++) {
                int ra = wm * 64 + mt * 16 + g;
                af[mt][0] = __float_as_uint(A0[ra * G1_ROW + kb + tig]);
                af[mt][1] = __float_as_uint(A0[(ra + 8) * G1_ROW + kb + tig]);
                af[mt][2] = __float_as_uint(A0[ra * G1_ROW + kb + tig + 4]);
                af[mt][3] = __float_as_uint(A0[(ra + 8) * G1_ROW + kb + tig + 4]);
            }
            uint32_t bf[4][2];
#pragma unroll
            for (int nt = 0; nt < 4; nt++) {
                int nb = wn * 32 + nt * 8 + g;
                bf[nt][0] = __float_as_uint(B0[nb * G1_ROW + kb + tig]);
                bf[nt][1] = __float_as_uint(B0[nb * G1_ROW + kb + tig + 4]);
            }
#pragma unroll
            for (int mt = 0; mt < 4; mt++)
#pragma unroll
                for (int nt = 0; nt < 4; nt++) {
                    asm volatile(
                        "mma.sync.aligned.m16n8k8.row.col.f32.tf32.tf32.f32 "
                        "{%0,%1,%2,%3}, {%4,%5,%6,%7}, {%8,%9}, {%0,%1,%2,%3};"
                        : "+f"(acc[mt][nt][0]), "+f"(acc[mt][nt][1]),
                          "+f"(acc[mt][nt][2]), "+f"(acc[mt][nt][3])
                        : "r"(af[mt][0]), "r"(af[mt][1]), "r"(af[mt][2]), "r"(af[mt][3]),
                          "r"(bf[nt][0]), "r"(bf[nt][1]));
                }
        }
        __syncthreads();
    }

#pragma unroll
    for (int mt = 0; mt < 4; mt++) {
#pragma unroll
        for (int half = 0; half < 2; half++) {
            int r = row0 + wm * 64 + mt * 16 + g + half * 8;
            if (r >= NN) continue;
#pragma unroll
            for (int nt = 0; nt < 4; nt++) {
                int c = wn * 32 + nt * 8 + tig * 2;
                float v0 = acc[mt][nt][half * 2]     + __ldg(bd + c);
                float v1 = acc[mt][nt][half * 2 + 1] + __ldg(bd + c + 1);
                v0 = v0 > 0.f ? v0 : 0.01f * v0;
                v1 = v1 > 0.f ? v1 : 0.01f * v1;
                *reinterpret_cast<float2*>(g_h + (size_t)r * EM + c) = make_float2(v0, v1);
            }
        }
    }
}

// ---------------- GEMM2 (tensor cores) + attention logits ----------------
#define G2_BM 128
#define G2_LDS 36
__global__ __launch_bounds__(256) void k_gemm2(const float* __restrict__ Wg,
                                               const float* __restrict__ att_s,
                                               const float* __restrict__ att_d) {
    __shared__ float As[G2_BM][G2_LDS];
    __shared__ float Bs[OD][G2_LDS];
    __shared__ float ps_sh[G2_BM][2], pd_sh[G2_BM][2];
    __shared__ float ats[OD], atd[OD];
    const int tid  = threadIdx.x;
    const int warp = tid >> 5;
    const int lane = tid & 31;
    const int g    = lane >> 2;
    const int tig  = lane & 3;
    const int wm   = warp >> 1;
    const int wn   = warp & 1;
    const int row0 = blockIdx.x * G2_BM;

    if (tid < OD) { ats[tid] = att_s[tid]; atd[tid] = att_d[tid]; }

    float acc[2][4][4];
#pragma unroll
    for (int i = 0; i < 2; i++)
#pragma unroll
        for (int j = 0; j < 4; j++)
#pragma unroll
            for (int r = 0; r < 4; r++) acc[i][j][r] = 0.f;

    for (int k0 = 0; k0 < EM; k0 += 32) {
#pragma unroll
        for (int i = 0; i < 4; i++) {
            int f  = tid + i * 256;
            int r  = f >> 3;
            int kq = f & 7;
            float4 v = make_float4(0.f, 0.f, 0.f, 0.f);
            int rg = row0 + r;
            if (rg < NN)
                v = *reinterpret_cast<const float4*>(g_h + (size_t)rg * EM + k0 + kq * 4);
            v.x = to_tf32(v.x); v.y = to_tf32(v.y);
            v.z = to_tf32(v.z); v.w = to_tf32(v.w);
            *reinterpret_cast<float4*>(&As[r][kq * 4]) = v;
        }
#pragma unroll
        for (int i = 0; i < 2; i++) {
            int f  = tid + i * 256;
            int c  = f >> 3;
            int kq = f & 7;
            float4 v = *reinterpret_cast<const float4*>(Wg + (size_t)c * EM + k0 + kq * 4);
            v.x = to_tf32(v.x); v.y = to_tf32(v.y);
            v.z = to_tf32(v.z); v.w = to_tf32(v.w);
            *reinterpret_cast<float4*>(&Bs[c][kq * 4]) = v;
        }
        __syncthreads();
#pragma unroll
        for (int ks = 0; ks < 4; ks++) {
            const int kb = ks * 8;
            uint32_t af[2][4];
#pragma unroll
            for (int mt = 0; mt < 2; mt++) {
                int ra = wm * 32 + mt * 16 + g;
                af[mt][0] = __float_as_uint(As[ra][kb + tig]);
                af[mt][1] = __float_as_uint(As[ra + 8][kb + tig]);
                af[mt][2] = __float_as_uint(As[ra][kb + tig + 4]);
                af[mt][3] = __float_as_uint(As[ra + 8][kb + tig + 4]);
            }
            uint32_t bf[4][2];
#pragma unroll
            for (int nt = 0; nt < 4; nt++) {
                int nb = wn * 32 + nt * 8 + g;
                bf[nt][0] = __float_as_uint(Bs[nb][kb + tig]);
                bf[nt][1] = __float_as_uint(Bs[nb][kb + tig + 4]);
            }
#pragma unroll
            for (int mt = 0; mt < 2; mt++)
#pragma unroll
                for (int nt = 0; nt < 4; nt++) {
                    asm volatile(
                        "mma.sync.aligned.m16n8k8.row.col.f32.tf32.tf32.f32 "
                        "{%0,%1,%2,%3}, {%4,%5,%6,%7}, {%8,%9}, {%0,%1,%2,%3};"
                        : "+f"(acc[mt][nt][0]), "+f"(acc[mt][nt][1]),
                          "+f"(acc[mt][nt][2]), "+f"(acc[mt][nt][3])
                        : "r"(af[mt][0]), "r"(af[mt][1]), "r"(af[mt][2]), "r"(af[mt][3]),
                          "r"(bf[nt][0]), "r"(bf[nt][1]));
                }
        }
        __syncthreads();
    }

#pragma unroll
    for (int mt = 0; mt < 2; mt++) {
#pragma unroll
        for (int half = 0; half < 2; half++) {
            int rloc = wm * 32 + mt * 16 + g + half * 8;
            int r = row0 + rloc;
            float ps = 0.f, pd = 0.f;
#pragma unroll
            for (int nt = 0; nt < 4; nt++) {
                int c = wn * 32 + nt * 8 + tig * 2;
                float v0 = acc[mt][nt][half * 2];
                float v1 = acc[mt][nt][half * 2 + 1];
                if (r < NN)
                    *reinterpret_cast<float2*>(g_g + (size_t)r * OD + c) = make_float2(v0, v1);
                ps = fmaf(v0, ats[c], fmaf(v1, ats[c + 1], ps));
                pd = fmaf(v0, atd[c], fmaf(v1, atd[c + 1], pd));
            }
            ps += __shfl_xor_sync(0xffffffffu, ps, 1);
            ps += __shfl_xor_sync(0xffffffffu, ps, 2);
            pd += __shfl_xor_sync(0xffffffffu, pd, 1);
            pd += __shfl_xor_sync(0xffffffffu, pd, 2);
            if (tig == 0) { ps_sh[rloc][wn] = ps; pd_sh[rloc][wn] = pd; }
        }
    }
    __syncthreads();
    if (tid < G2_BM) {
        int r = row0 + tid;
        if (r < NN) {
            g_as[r] = ps_sh[tid][0] + ps_sh[tid][1];
            g_ad[r] = pd_sh[tid][0] + pd_sh[tid][1];
        }
    }
}

// ---------------- fused softmax + gather accumulate ----------------
// 1 warp per dst, float2 per lane (64 cols). 32-edge batches, processed as two
// 16-edge halves with 16-deep float2 staging (32 regs -> no spill, unlike R9's
// 32-deep float2). Per edge: 1 LDG.64 + 2 SHFL + 2 FMA on ONE warp.
__global__ __launch_bounds__(256) void k_accum(float* __restrict__ out,
                                               const float* __restrict__ bg) {
    const unsigned FULL = 0xffffffffu;
    int w    = (blockIdx.x * blockDim.x + threadIdx.x) >> 5;
    int lane = threadIdx.x & 31;
    if (w >= NN) return;
    int beg = g_off[w];
    int cnt = g_cnt[w];
    float a_d = g_ad[w];

    // self loop
    float e0 = g_as[w] + a_d;
    e0 = e0 > 0.f ? e0 : 0.2f * e0;
    float wt_self = __expf(e0);
    float2 gw = *reinterpret_cast<const float2*>(g_g + (size_t)w * OD + lane * 2);
    float acc0 = wt_self * gw.x, acc1 = wt_self * gw.y;
    float den_l = (lane == 0) ? wt_self : 0.f;

    int end = beg + cnt;
    for (int j = beg; j < end; j += 32) {
        int m = end - j;
        if (m > 32) m = 32;
        int   s_l  = w;
        float wt_l = 0.f;
        if (lane < m) {
            s_l = g_esrc[j + lane];
            float e = g_as[s_l] + a_d;
            e = e > 0.f ? e : 0.2f * e;
            wt_l = __expf(e);
        }
        den_l += wt_l;
#pragma unroll
        for (int hh = 0; hh < 2; hh++) {
            float2 gvs[16];
#pragma unroll
            for (int u = 0; u < 16; u++) {
                int s = __shfl_sync(FULL, s_l, hh * 16 + u);
                gvs[u] = *reinterpret_cast<const float2*>(g_g + (size_t)s * OD + lane * 2);
            }
#pragma unroll
            for (int u = 0; u < 16; u++) {
                float wt = __shfl_sync(FULL, wt_l, hh * 16 + u);
                acc0 = fmaf(wt, gvs[u].x, acc0);
                acc1 = fmaf(wt, gvs[u].y, acc1);
            }
        }
    }
#pragma unroll
    for (int o = 16; o > 0; o >>= 1)
        den_l += __shfl_xor_sync(FULL, den_l, o);
    float inv = 1.f / den_l;
    int c = lane * 2;
    float2 b2 = *reinterpret_cast<const float2*>(bg + c);
    *reinterpret_cast<float2*>(out + (size_t)w * OD + c) =
        make_float2(acc0 * inv + b2.x, acc1 * inv + b2.y);
}

// ---------------- launch ----------------
extern "C" void kernel_launch(void* const* d_in, const int* in_sizes, int n_in,
                              void* d_out, int out_size) {
    const float* x   = (const float*)d_in[0];
    const int*   ei  = (const int*)  d_in[1];
    const float* Wd  = (const float*)d_in[2];
    const float* bd  = (const float*)d_in[3];
    const float* Wg  = (const float*)d_in[4];
    const float* ats = (const float*)d_in[5];
    const float* atd = (const float*)d_in[6];
    const float* bg  = (const float*)d_in[7];
    float* out = (float*)d_out;

    const int E = in_sizes[1] / 2;

    static cudaStream_t s2 = nullptr;
    static cudaEvent_t ev_fork = nullptr, ev_join = nullptr;
    static void* cnt_ptr = nullptr;
    if (!s2) {
        cudaStreamCreate(&s2);
        cudaEventCreateWithFlags(&ev_fork, cudaEventDisableTiming);
        cudaEventCreateWithFlags(&ev_join, cudaEventDisableTiming);
        cudaGetSymbolAddress(&cnt_ptr, g_cnt);
        cudaFuncSetAttribute(k_gemm1, cudaFuncAttributeMaxDynamicSharedMemorySize, G1_SMEM);
    }

    // fork: CSR build on s2 (memset is not a kernel launch)
    cudaEventRecord(ev_fork, 0);
    cudaStreamWaitEvent(s2, ev_fork, 0);

    cudaMemsetAsync(cnt_ptr, 0, NN * sizeof(int), s2);
    k_hist<<<(E + 255) / 256, 256, 0, s2>>>(ei, E);          // launch 1
    k_scan1<<<SCAN_B, 256, 0, s2>>>();                       // launch 2
    k_scan2<<<1, 256, 0, s2>>>();                            // launch 3

    k_gemm1<<<(NN + G1_BM - 1) / G1_BM, 256, G1_SMEM>>>(x, Wd, bd);  // launch 4 (profiled)

    k_scan3<<<SCAN_B, 256, 0, s2>>>();                       // launch 5
    k_scatter<<<(E + 255) / 256, 256, 0, s2>>>(ei, E);       // launch 6
    cudaEventRecord(ev_join, s2);

    k_gemm2<<<(NN + G2_BM - 1) / G2_BM, 256>>>(Wg, ats, atd);

    cudaStreamWaitEvent(0, ev_join, 0);
    k_accum<<<(NN * 32 + 255) / 256, 256>>>(out, bg);
}

// round 13
// speedup vs baseline: 1.8012x; 1.0022x over previous
#include <cuda_runtime.h>
#include <cstdint>

#define NN 50000
#define KD 512
#define EM 128
#define OD 64
#define EE 1600000
#define SCAN_B 196            // 196 * 256 = 50176 >= NN

// ---------------- scratch (device globals) ----------------
__device__ float g_h[(size_t)NN * EM];
__device__ float g_g[(size_t)NN * OD];
__device__ float g_as[NN];
__device__ float g_ad[NN];
__device__ int   g_cnt[NN];
__device__ int   g_off[NN];
__device__ int   g_pos[NN];
__device__ int   g_esrc[EE];
__device__ int   g_bsum[SCAN_B];
__device__ int   g_boff[SCAN_B];

__device__ __forceinline__ float to_tf32(float x) {
    float r;
    asm("cvt.rna.tf32.f32 %0, %1;" : "=f"(r) : "f"(x));
    return r;
}

// ---------------- CSR build (parallel, coalesced) ----------------
__global__ void k_hist(const int* __restrict__ ei, int E) {
    int i = blockIdx.x * blockDim.x + threadIdx.x;
    if (i < E) atomicAdd(g_cnt + ei[E + i], 1);
}

__global__ __launch_bounds__(256) void k_scan1() {
    __shared__ int sh[256];
    int t = threadIdx.x;
    int i = blockIdx.x * 256 + t;
    int v = (i < NN) ? g_cnt[i] : 0;
    sh[t] = v;
    __syncthreads();
#pragma unroll
    for (int o = 128; o > 0; o >>= 1) {
        if (t < o) sh[t] += sh[t + o];
        __syncthreads();
    }
    if (t == 0) g_bsum[blockIdx.x] = sh[0];
}

__global__ __launch_bounds__(256) void k_scan2() {
    __shared__ int sh[256];
    int t = threadIdx.x;
    int v = (t < SCAN_B) ? g_bsum[t] : 0;
    sh[t] = v;
    __syncthreads();
#pragma unroll
    for (int o = 1; o < 256; o <<= 1) {
        int u = (t >= o) ? sh[t - o] : 0;
        __syncthreads();
        sh[t] += u;
        __syncthreads();
    }
    if (t < SCAN_B) g_boff[t] = sh[t] - v;
}

__global__ __launch_bounds__(256) void k_scan3() {
    __shared__ int sh[256];
    int t = threadIdx.x;
    int i = blockIdx.x * 256 + t;
    int v = (i < NN) ? g_cnt[i] : 0;
    sh[t] = v;
    __syncthreads();
#pragma unroll
    for (int o = 1; o < 256; o <<= 1) {
        int u = (t >= o) ? sh[t - o] : 0;
        __syncthreads();
        sh[t] += u;
        __syncthreads();
    }
    if (i < NN) {
        int off = g_boff[blockIdx.x] + sh[t] - v;
        g_off[i] = off;
        g_pos[i] = off;
    }
}

__global__ void k_scatter(const int* __restrict__ ei, int E) {
    int i = blockIdx.x * blockDim.x + threadIdx.x;
    if (i >= E) return;
    int s = ei[i];
    int d = ei[E + i];
    int p = atomicAdd(g_pos + d, 1);
    g_esrc[p] = s;
}

// ---------------- GEMM1: tf32 mma + 2-stage cp.async pipeline ----------------
// Fragment loads use cvt.rna (RNA): RZ raw-bit feeding was measured to inflate
// rel_err 2.3e-4 -> 7.4e-4 (coherent truncation bias over K=512).
#define G1_BM 128
#define G1_BK 32
#define G1_ROW 36
#define G1_TILE (G1_BM * G1_ROW)
#define G1_SMEM (4 * G1_TILE * 4)

__global__ __launch_bounds__(256) void k_gemm1(const float* __restrict__ X,
                                               const float* __restrict__ Wd,
                                               const float* __restrict__ bd) {
    extern __shared__ float smem[];
    float* As = smem;                 // [2][128][36]
    float* Bs = smem + 2 * G1_TILE;   // [2][128][36]
    const int tid  = threadIdx.x;
    const int warp = tid >> 5;
    const int lane = tid & 31;
    const int g    = lane >> 2;
    const int tig  = lane & 3;
    const int wm   = warp >> 2;
    const int wn   = warp & 3;
    const int row0 = blockIdx.x * G1_BM;

    const uint32_t a_base = (uint32_t)__cvta_generic_to_shared(As);
    const uint32_t b_base = (uint32_t)__cvta_generic_to_shared(Bs);

    float acc[4][4][4];
#pragma unroll
    for (int i = 0; i < 4; i++)
#pragma unroll
        for (int j = 0; j < 4; j++)
#pragma unroll
            for (int r = 0; r < 4; r++) acc[i][j][r] = 0.f;

    auto load_stage = [&](int st, int k0) {
#pragma unroll
        for (int i = 0; i < 4; i++) {
            int f  = tid + i * 256;
            int r  = f >> 3;
            int kq = f & 7;
            int rg = row0 + r;
            if (rg > NN - 1) rg = NN - 1;    // clamp (stores masked in epilogue)
            const float* src = X + (size_t)rg * KD + k0 + kq * 4;
            uint32_t dst = a_base + (uint32_t)((st * G1_TILE + r * G1_ROW + kq * 4) * 4);
            asm volatile("cp.async.cg.shared.global [%0], [%1], 16;"
                         :: "r"(dst), "l"(src));
        }
#pragma unroll
        for (int i = 0; i < 4; i++) {
            int f  = tid + i * 256;
            int c  = f >> 3;
            int kq = f & 7;
            const float* src = Wd + (size_t)c * KD + k0 + kq * 4;
            uint32_t dst = b_base + (uint32_t)((st * G1_TILE + c * G1_ROW + kq * 4) * 4);
            asm volatile("cp.async.cg.shared.global [%0], [%1], 16;"
                         :: "r"(dst), "l"(src));
        }
        asm volatile("cp.async.commit_group;");
    };

    const int NCH = KD / G1_BK;   // 16
    load_stage(0, 0);
    for (int kt = 0; kt < NCH; kt++) {
        int st = kt & 1;
        if (kt + 1 < NCH) {
            load_stage(st ^ 1, (kt + 1) * G1_BK);
            asm volatile("cp.async.wait_group 1;");
        } else {
            asm volatile("cp.async.wait_group 0;");
        }
        __syncthreads();

        const float* A0 = As + st * G1_TILE;
        const float* B0 = Bs + st * G1_TILE;
#pragma unroll
        for (int ks = 0; ks < 4; ks++) {
            const int kb = ks * 8;
            uint32_t af[4][4];
#pragma unroll
            for (int mt = 0; mt < 4; mt++) {
                int ra = wm * 64 + mt * 16 + g;
                af[mt][0] = __float_as_uint(to_tf32(A0[ra * G1_ROW + kb + tig]));
                af[mt][1] = __float_as_uint(to_tf32(A0[(ra + 8) * G1_ROW + kb + tig]));
                af[mt][2] = __float_as_uint(to_tf32(A0[ra * G1_ROW + kb + tig + 4]));
                af[mt][3] = __float_as_uint(to_tf32(A0[(ra + 8) * G1_ROW + kb + tig + 4]));
            }
            uint32_t bf[4][2];
#pragma unroll
            for (int nt = 0; nt < 4; nt++) {
                int nb = wn * 32 + nt * 8 + g;
                bf[nt][0] = __float_as_uint(to_tf32(B0[nb * G1_ROW + kb + tig]));
                bf[nt][1] = __float_as_uint(to_tf32(B0[nb * G1_ROW + kb + tig + 4]));
            }
#pragma unroll
            for (int mt = 0; mt < 4; mt++)
#pragma unroll
                for (int nt = 0; nt < 4; nt++) {
                    asm volatile(
                        "mma.sync.aligned.m16n8k8.row.col.f32.tf32.tf32.f32 "
                        "{%0,%1,%2,%3}, {%4,%5,%6,%7}, {%8,%9}, {%0,%1,%2,%3};"
                        : "+f"(acc[mt][nt][0]), "+f"(acc[mt][nt][1]),
                          "+f"(acc[mt][nt][2]), "+f"(acc[mt][nt][3])
                        : "r"(af[mt][0]), "r"(af[mt][1]), "r"(af[mt][2]), "r"(af[mt][3]),
                          "r"(bf[nt][0]), "r"(bf[nt][1]));
                }
        }
        __syncthreads();
    }

#pragma unroll
    for (int mt = 0; mt < 4; mt++) {
#pragma unroll
        for (int half = 0; half < 2; half++) {
            int r = row0 + wm * 64 + mt * 16 + g + half * 8;
            if (r >= NN) continue;
#pragma unroll
            for (int nt = 0; nt < 4; nt++) {
                int c = wn * 32 + nt * 8 + tig * 2;
                float v0 = acc[mt][nt][half * 2]     + __ldg(bd + c);
                float v1 = acc[mt][nt][half * 2 + 1] + __ldg(bd + c + 1);
                v0 = v0 > 0.f ? v0 : 0.01f * v0;
                v1 = v1 > 0.f ? v1 : 0.01f * v1;
                *reinterpret_cast<float2*>(g_h + (size_t)r * EM + c) = make_float2(v0, v1);
            }
        }
    }
}

// ---------------- GEMM2 (tensor cores) + attention logits ----------------
#define G2_BM 128
#define G2_LDS 36
__global__ __launch_bounds__(256) void k_gemm2(const float* __restrict__ Wg,
                                               const float* __restrict__ att_s,
                                               const float* __restrict__ att_d) {
    __shared__ float As[G2_BM][G2_LDS];
    __shared__ float Bs[OD][G2_LDS];
    __shared__ float ps_sh[G2_BM][2], pd_sh[G2_BM][2];
    __shared__ float ats[OD], atd[OD];
    const int tid  = threadIdx.x;
    const int warp = tid >> 5;
    const int lane = tid & 31;
    const int g    = lane >> 2;
    const int tig  = lane & 3;
    const int wm   = warp >> 1;
    const int wn   = warp & 1;
    const int row0 = blockIdx.x * G2_BM;

    if (tid < OD) { ats[tid] = att_s[tid]; atd[tid] = att_d[tid]; }

    float acc[2][4][4];
#pragma unroll
    for (int i = 0; i < 2; i++)
#pragma unroll
        for (int j = 0; j < 4; j++)
#pragma unroll
            for (int r = 0; r < 4; r++) acc[i][j][r] = 0.f;

    for (int k0 = 0; k0 < EM; k0 += 32) {
#pragma unroll
        for (int i = 0; i < 4; i++) {
            int f  = tid + i * 256;
            int r  = f >> 3;
            int kq = f & 7;
            float4 v = make_float4(0.f, 0.f, 0.f, 0.f);
            int rg = row0 + r;
            if (rg < NN)
                v = *reinterpret_cast<const float4*>(g_h + (size_t)rg * EM + k0 + kq * 4);
            v.x = to_tf32(v.x); v.y = to_tf32(v.y);
            v.z = to_tf32(v.z); v.w = to_tf32(v.w);
            *reinterpret_cast<float4*>(&As[r][kq * 4]) = v;
        }
#pragma unroll
        for (int i = 0; i < 2; i++) {
            int f  = tid + i * 256;
            int c  = f >> 3;
            int kq = f & 7;
            float4 v = *reinterpret_cast<const float4*>(Wg + (size_t)c * EM + k0 + kq * 4);
            v.x = to_tf32(v.x); v.y = to_tf32(v.y);
            v.z = to_tf32(v.z); v.w = to_tf32(v.w);
            *reinterpret_cast<float4*>(&Bs[c][kq * 4]) = v;
        }
        __syncthreads();
#pragma unroll
        for (int ks = 0; ks < 4; ks++) {
            const int kb = ks * 8;
            uint32_t af[2][4];
#pragma unroll
            for (int mt = 0; mt < 2; mt++) {
                int ra = wm * 32 + mt * 16 + g;
                af[mt][0] = __float_as_uint(As[ra][kb + tig]);
                af[mt][1] = __float_as_uint(As[ra + 8][kb + tig]);
                af[mt][2] = __float_as_uint(As[ra][kb + tig + 4]);
                af[mt][3] = __float_as_uint(As[ra + 8][kb + tig + 4]);
            }
            uint32_t bf[4][2];
#pragma unroll
            for (int nt = 0; nt < 4; nt++) {
                int nb = wn * 32 + nt * 8 + g;
                bf[nt][0] = __float_as_uint(Bs[nb][kb + tig]);
                bf[nt][1] = __float_as_uint(Bs[nb][kb + tig + 4]);
            }
#pragma unroll
            for (int mt = 0; mt < 2; mt++)
#pragma unroll
                for (int nt = 0; nt < 4; nt++) {
                    asm volatile(
                        "mma.sync.aligned.m16n8k8.row.col.f32.tf32.tf32.f32 "
                        "{%0,%1,%2,%3}, {%4,%5,%6,%7}, {%8,%9}, {%0,%1,%2,%3};"
                        : "+f"(acc[mt][nt][0]), "+f"(acc[mt][nt][1]),
                          "+f"(acc[mt][nt][2]), "+f"(acc[mt][nt][3])
                        : "r"(af[mt][0]), "r"(af[mt][1]), "r"(af[mt][2]), "r"(af[mt][3]),
                          "r"(bf[nt][0]), "r"(bf[nt][1]));
                }
        }
        __syncthreads();
    }

#pragma unroll
    for (int mt = 0; mt < 2; mt++) {
#pragma unroll
        for (int half = 0; half < 2; half++) {
            int rloc = wm * 32 + mt * 16 + g + half * 8;
            int r = row0 + rloc;
            float ps = 0.f, pd = 0.f;
#pragma unroll
            for (int nt = 0; nt < 4; nt++) {
                int c = wn * 32 + nt * 8 + tig * 2;
                float v0 = acc[mt][nt][half * 2];
                float v1 = acc[mt][nt][half * 2 + 1];
                if (r < NN)
                    *reinterpret_cast<float2*>(g_g + (size_t)r * OD + c) = make_float2(v0, v1);
                ps = fmaf(v0, ats[c], fmaf(v1, ats[c + 1], ps));
                pd = fmaf(v0, atd[c], fmaf(v1, atd[c + 1], pd));
            }
            ps += __shfl_xor_sync(0xffffffffu, ps, 1);
            ps += __shfl_xor_sync(0xffffffffu, ps, 2);
            pd += __shfl_xor_sync(0xffffffffu, pd, 1);
            pd += __shfl_xor_sync(0xffffffffu, pd, 2);
            if (tig == 0) { ps_sh[rloc][wn] = ps; pd_sh[rloc][wn] = pd; }
        }
    }
    __syncthreads();
    if (tid < G2_BM) {
        int r = row0 + tid;
        if (r < NN) {
            g_as[r] = ps_sh[tid][0] + ps_sh[tid][1];
            g_ad[r] = pd_sh[tid][0] + pd_sh[tid][1];
        }
    }
}

// ---------------- fused softmax + gather accumulate (pipelined weight chain) --
// 1 warp per dst, float2 per lane. The esrc->g_as->expf chain for batch k+1 is
// issued BEFORE batch k's gathers/FMAs, so its ~1100cyc latency overlaps them.
__global__ __launch_bounds__(256) void k_accum(float* __restrict__ out,
                                               const float* __restrict__ bg) {
    const unsigned FULL = 0xffffffffu;
    int w    = (blockIdx.x * blockDim.x + threadIdx.x) >> 5;
    int lane = threadIdx.x & 31;
    if (w >= NN) return;
    int beg = g_off[w];
    int end = beg + g_cnt[w];
    float a_d = g_ad[w];

    // self loop
    float e0 = g_as[w] + a_d;
    e0 = e0 > 0.f ? e0 : 0.2f * e0;
    float wt_self = __expf(e0);
    float2 gw = *reinterpret_cast<const float2*>(g_g + (size_t)w * OD + lane * 2);
    float acc0 = wt_self * gw.x, acc1 = wt_self * gw.y;
    float den_l = (lane == 0) ? wt_self : 0.f;

    // prologue: chain for first batch
    int   s_l  = w;
    float wt_l = 0.f;
    if (beg < end && beg + lane < end) {
        s_l = g_esrc[beg + lane];
        float e = g_as[s_l] + a_d;
        e = e > 0.f ? e : 0.2f * e;
        wt_l = __expf(e);
    }

    for (int j = beg; j < end; j += 32) {
        // prefetch next batch's chain (independent of current batch work)
        int   jn   = j + 32;
        int   s_nl = w;
        float a_nl = 0.f;
        bool  nv   = false;
        if (jn < end && jn + lane < end) {
            s_nl = g_esrc[jn + lane];
            a_nl = g_as[s_nl];
            nv   = true;
        }

        den_l += wt_l;
#pragma unroll
        for (int hh = 0; hh < 2; hh++) {
            float2 gvs[16];
#pragma unroll
            for (int u = 0; u < 16; u++) {
                int s = __shfl_sync(FULL, s_l, hh * 16 + u);
                gvs[u] = *reinterpret_cast<const float2*>(g_g + (size_t)s * OD + lane * 2);
            }
#pragma unroll
            for (int u = 0; u < 16; u++) {
                float wt = __shfl_sync(FULL, wt_l, hh * 16 + u);
                acc0 = fmaf(wt, gvs[u].x, acc0);
                acc1 = fmaf(wt, gvs[u].y, acc1);
            }
        }

        // finish next chain (loads have been in flight during gathers/FMAs)
        float e = a_nl + a_d;
        e = e > 0.f ? e : 0.2f * e;
        wt_l = nv ? __expf(e) : 0.f;
        s_l  = s_nl;
    }
#pragma unroll
    for (int o = 16; o > 0; o >>= 1)
        den_l += __shfl_xor_sync(FULL, den_l, o);
    float inv = 1.f / den_l;
    int c = lane * 2;
    float2 b2 = *reinterpret_cast<const float2*>(bg + c);
    *reinterpret_cast<float2*>(out + (size_t)w * OD + c) =
        make_float2(acc0 * inv + b2.x, acc1 * inv + b2.y);
}

// ---------------- launch ----------------
extern "C" void kernel_launch(void* const* d_in, const int* in_sizes, int n_in,
                              void* d_out, int out_size) {
    const float* x   = (const float*)d_in[0];
    const int*   ei  = (const int*)  d_in[1];
    const float* Wd  = (const float*)d_in[2];
    const float* bd  = (const float*)d_in[3];
    const float* Wg  = (const float*)d_in[4];
    const float* ats = (const float*)d_in[5];
    const float* atd = (const float*)d_in[6];
    const float* bg  = (const float*)d_in[7];
    float* out = (float*)d_out;

    const int E = in_sizes[1] / 2;

    static cudaStream_t s2 = nullptr;
    static cudaEvent_t ev_fork = nullptr, ev_join = nullptr;
    static void* cnt_ptr = nullptr;
    if (!s2) {
        cudaStreamCreate(&s2);
        cudaEventCreateWithFlags(&ev_fork, cudaEventDisableTiming);
        cudaEventCreateWithFlags(&ev_join, cudaEventDisableTiming);
        cudaGetSymbolAddress(&cnt_ptr, g_cnt);
        cudaFuncSetAttribute(k_gemm1, cudaFuncAttributeMaxDynamicSharedMemorySize, G1_SMEM);
    }

    // fork: CSR build on s2 (memset is not a kernel launch)
    cudaEventRecord(ev_fork, 0);
    cudaStreamWaitEvent(s2, ev_fork, 0);

    cudaMemsetAsync(cnt_ptr, 0, NN * sizeof(int), s2);
    k_hist<<<(E + 255) / 256, 256, 0, s2>>>(ei, E);          // launch 1
    k_scan1<<<SCAN_B, 256, 0, s2>>>();                       // launch 2
    k_scan2<<<1, 256, 0, s2>>>();                            // launch 3

    k_gemm1<<<(NN + G1_BM - 1) / G1_BM, 256, G1_SMEM>>>(x, Wd, bd);  // launch 4 (profiled)

    k_scan3<<<SCAN_B, 256, 0, s2>>>();                       // launch 5
    k_scatter<<<(E + 255) / 256, 256, 0, s2>>>(ei, E);       // launch 6
    cudaEventRecord(ev_join, s2);

    k_gemm2<<<(NN + G2_BM - 1) / G2_BM, 256>>>(Wg, ats, atd);

    cudaStreamWaitEvent(0, ev_join, 0);
    k_accum<<<(NN * 32 + 255) / 256, 256>>>(out, bg);
}